// round 7
// baseline (speedup 1.0000x reference)
#include <cuda_runtime.h>

// SSIM loss, fused separable, cp.async 3-deep row pipeline + packed f32x2 math.
// pred, gt: f32 [16,3,512,512] -> out: f32 scalar = 1 - mean(ssim_map)

#define IMG_H 512
#define IMG_W 512
#define N_IMG 48
#define TH 64
#define NROWS (TH + 10)        // 74 input rows per strip
#define NITER 77               // 7*11 (ring period 11 -> const-folded slots)
#define SPAD 8
#define SW (IMG_W + 2 * SPAD)  // 528
#define NSTRIPS (IMG_H / TH)   // 8
#define NBLK (N_IMG * NSTRIPS) // 384
#define NSTAGE 4
#define C1F 0.0001f
#define C2F 0.0009f

#define GW0 0.00102838f
#define GW1 0.00759876f
#define GW2 0.03600078f
#define GW3 0.10936069f
#define GW4 0.21300553f
#define GW5 0.26601172f

__device__ float        g_partials[NBLK];
__device__ unsigned int g_count;

typedef unsigned long long u64;

static __device__ __forceinline__ u64 pack2(float lo, float hi) {
    u64 r; asm("mov.b64 %0, {%1, %2};" : "=l"(r) : "f"(lo), "f"(hi)); return r;
}
static __device__ __forceinline__ void unpack2(u64 v, float& lo, float& hi) {
    asm("mov.b64 {%0, %1}, %2;" : "=f"(lo), "=f"(hi) : "l"(v));
}
static __device__ __forceinline__ u64 fma2(u64 a, u64 b, u64 c) {
    u64 d; asm("fma.rn.f32x2 %0, %1, %2, %3;" : "=l"(d) : "l"(a), "l"(b), "l"(c)); return d;
}
static __device__ __forceinline__ u64 mul2(u64 a, u64 b) {
    u64 d; asm("mul.rn.f32x2 %0, %1, %2;" : "=l"(d) : "l"(a), "l"(b)); return d;
}
static __device__ __forceinline__ void cp16(void* dst_smem, const void* src_g) {
    unsigned int d = (unsigned int)__cvta_generic_to_shared(dst_smem);
    asm volatile("cp.async.cg.shared.global [%0], [%1], 16;\n" :: "r"(d), "l"(src_g));
}
static __device__ __forceinline__ void cp_commit() {
    asm volatile("cp.async.commit_group;\n" ::: "memory");
}
static __device__ __forceinline__ void cp_wait2() {
    asm volatile("cp.async.wait_group 2;\n" ::: "memory");
}

__global__ __launch_bounds__(512, 1)
void ssim_main(const float* __restrict__ pred, const float* __restrict__ gt,
               float* __restrict__ out)
{
    __shared__ float sx[NSTAGE][SW];
    __shared__ float sy[NSTAGE][SW];
    __shared__ float sred[16];
    __shared__ unsigned int s_last;

    const int c     = threadIdx.x;          // one thread per output column
    const int strip = blockIdx.x;
    const int img   = blockIdx.y;
    const int bid   = img * NSTRIPS + strip;
    const int row0  = strip * TH;
    const float* px = pred + (size_t)img * (IMG_H * IMG_W);
    const float* py = gt   + (size_t)img * (IMG_H * IMG_W);

    const float Wt[6] = {GW0, GW1, GW2, GW3, GW4, GW5};

    // horizontal weights, parity-packed (lane = value at base+2m / base+2m+1)
    u64 Wh[6];
    if (c & 1) {   // base = c-5: taps -5..6, tap +6 weight 0
        Wh[0] = pack2(GW0, GW1); Wh[1] = pack2(GW2, GW3); Wh[2] = pack2(GW4, GW5);
        Wh[3] = pack2(GW4, GW3); Wh[4] = pack2(GW2, GW1); Wh[5] = pack2(GW0, 0.f);
    } else {       // base = c-6: taps -6..5, tap -6 weight 0
        Wh[0] = pack2(0.f, GW0); Wh[1] = pack2(GW1, GW2); Wh[2] = pack2(GW3, GW4);
        Wh[3] = pack2(GW5, GW4); Wh[4] = pack2(GW3, GW2); Wh[5] = pack2(GW1, GW0);
    }
    u64 Wv[6];
    #pragma unroll
    for (int i = 0; i < 6; ++i) Wv[i] = pack2(Wt[i], Wt[i]);

    // zero column halos for all stages (never rewritten)
    if (c < SPAD) {
        #pragma unroll
        for (int s = 0; s < NSTAGE; ++s) {
            sx[s][c] = 0.f; sy[s][c] = 0.f;
            sx[s][SPAD + IMG_W + c] = 0.f; sy[s][SPAD + IMG_W + c] = 0.f;
        }
    }

    // producer mapping: threads 0-127 copy the x row, 128-255 the y row (16B each)
    const bool isProd = (c < 256);
    const bool isY    = (c & 128) != 0;
    const int  pcol   = (c & 127) * 4;

    // issue global row (row0-5+rr) into stage rr&3; zero-fill if outside image
    auto issue = [&](int rr) {
        if (rr < NITER) {
            const int st = rr & NSTAGE - 1;
            const int gr = row0 - 5 + rr;
            if (isProd) {
                float* dst = (isY ? sy[st] : sx[st]) + SPAD + pcol;
                if ((unsigned)gr < IMG_H) {
                    const float* src = (isY ? py : px) + gr * IMG_W + pcol;
                    cp16(dst, src);
                } else {
                    *(float4*)dst = make_float4(0.f, 0.f, 0.f, 0.f);
                }
            }
        }
        cp_commit();
    };

    // prologue: 3 rows in flight
    issue(0); issue(1); issue(2);

    // vertical ring accumulators
    u64 amu[11], avar[11]; float axy[11];
    #pragma unroll
    for (int j = 0; j < 11; ++j) { amu[j] = 0ULL; avar[j] = 0ULL; axy[j] = 0.f; }

    const int xoff = SPAD + c - 6 + (c & 1);   // 8B-aligned base for pair loads
    float tsum = 0.f;

    #pragma unroll 1
    for (int rb = 0; rb < NITER; rb += 11) {
        #pragma unroll
        for (int i = 0; i < 11; ++i) {
            const int r = rb + i;

            cp_wait2();               // row r landed
            __syncthreads();
            issue(r + 3);             // refill stage (r-1)&3

            const int st = r & (NSTAGE - 1);
            const float* rx = sx[st] + xoff;
            const float* ry = sy[st] + xoff;

            // horizontal 11-tap conv via 6 aligned pair loads per array
            u64 hx = 0ULL, hy = 0ULL, hxx = 0ULL, hyy = 0ULL, hxy = 0ULL;
            #pragma unroll
            for (int m = 0; m < 6; ++m) {
                const u64 X = *(const u64*)(rx + 2 * m);   // LDS.64
                const u64 Y = *(const u64*)(ry + 2 * m);
                hx  = fma2(X, Wh[m], hx);
                hy  = fma2(Y, Wh[m], hy);
                hxx = fma2(mul2(X, X), Wh[m], hxx);
                hyy = fma2(mul2(Y, Y), Wh[m], hyy);
                hxy = fma2(mul2(X, Y), Wh[m], hxy);
            }
            float a0, a1, fhx, fhy, fhxx, fhyy, fhxy;
            unpack2(hx,  a0, a1); fhx  = a0 + a1;
            unpack2(hy,  a0, a1); fhy  = a0 + a1;
            unpack2(hxx, a0, a1); fhxx = a0 + a1;
            unpack2(hyy, a0, a1); fhyy = a0 + a1;
            unpack2(hxy, a0, a1); fhxy = a0 + a1;
            const u64 hmu  = pack2(fhx,  fhy);
            const u64 hvar = pack2(fhxx, fhyy);

            // vertical scatter into ring (slot indices constant-folded)
            #pragma unroll
            for (int j = 0; j < 11; ++j) {
                const int s  = (i + 1 + j) % 11;
                const int wi = (j < 6) ? j : 10 - j;
                amu[s]  = fma2(hmu,  Wv[wi], amu[s]);
                avar[s] = fma2(hvar, Wv[wi], avar[s]);
                axy[s]  = fmaf(Wt[wi], fhxy, axy[s]);
            }

            // slot (i+1)%11 completed -> output row r-10
            const int s0 = (i + 1) % 11;
            const int o  = r - 10;
            if (o >= 0 && o < TH) {
                float mu1, mu2, Exx, Eyy;
                unpack2(amu[s0], mu1, mu2);
                unpack2(avar[s0], Exx, Eyy);
                const float m11 = mu1 * mu1;
                const float m22 = mu2 * mu2;
                const float m12 = mu1 * mu2;
                const float v1  = Exx - m11;
                const float v2  = Eyy - m22;
                const float v12 = axy[s0] - m12;
                const float num = (2.f * m12 + C1F) * (2.f * v12 + C2F);
                const float den = (m11 + m22 + C1F) * (v1 + v2 + C2F);
                tsum += __fdividef(num, den);
            }
            amu[s0] = 0ULL; avar[s0] = 0ULL; axy[s0] = 0.f;
        }
    }

    // deterministic block reduction
    #pragma unroll
    for (int off = 16; off > 0; off >>= 1)
        tsum += __shfl_down_sync(0xffffffffu, tsum, off);
    if ((c & 31) == 0) sred[c >> 5] = tsum;
    __syncthreads();
    if (c == 0) {
        float s = 0.f;
        #pragma unroll
        for (int w = 0; w < 16; ++w) s += sred[w];
        g_partials[bid] = s;
        __threadfence();
        const unsigned int old = atomicAdd(&g_count, 1u);
        s_last = (old == NBLK - 1) ? 1u : 0u;
    }
    __syncthreads();

    // last block reduces the 384 partials (fixed order -> deterministic)
    if (s_last) {
        float v = (c < NBLK) ? __ldcg(&g_partials[c]) : 0.f;
        #pragma unroll
        for (int off = 16; off > 0; off >>= 1)
            v += __shfl_down_sync(0xffffffffu, v, off);
        if ((c & 31) == 0) sred[c >> 5] = v;
        __syncthreads();
        if (c == 0) {
            float s = 0.f;
            #pragma unroll
            for (int w = 0; w < 16; ++w) s += sred[w];
            out[0] = 1.0f - s * (1.0f / 12582912.0f);
            g_count = 0;               // re-arm for next graph replay
        }
    }
}

extern "C" void kernel_launch(void* const* d_in, const int* in_sizes, int n_in,
                              void* d_out, int out_size)
{
    (void)in_sizes; (void)n_in; (void)out_size;
    const float* pred = (const float*)d_in[0];
    const float* gt   = (const float*)d_in[1];

    dim3 grid(NSTRIPS, N_IMG);              // (8, 48) = 384 blocks
    ssim_main<<<grid, IMG_W>>>(pred, gt, (float*)d_out);
}